// round 3
// baseline (speedup 1.0000x reference)
#include <cuda_runtime.h>

// CollisionLoss — single fused kernel.
//  d_in[0] sdc_traj_all        (1, F, 2) f32
//  d_in[1] sdc_planning_gt     (1, F, 3) f32  (theta = [...,2])
//  d_in[2] sdc_planning_gt_mask (unused)
//  d_in[3] future_gt_corners   (F, N, 4, 2) f32  [192 MB]
//  d_in[4] box_mask            (F, N) bool as int32 [24 MB]
// output: 1 x f32

#define F_FRAMES 6
#define N_PTS    1000000u
#define TOTAL    (F_FRAMES * N_PTS)
#define NQUADS   (TOTAL / 4u)          /* 1,500,000 ; N_PTS % 4 == 0 */
#define W_BOX    2.35f                 /* 1.85 + 0.5 */
#define H_BOX    4.584f                /* 4.084 + 0.5 */

#define NTHREADS 256
#define NBLOCKS  2368                  /* 148 SMs * 16 */

__device__ __forceinline__ float4 ldcs4(const float4* p) {
    float4 v;
    asm volatile("ld.global.cs.v4.f32 {%0,%1,%2,%3}, [%4];"
                 : "=f"(v.x), "=f"(v.y), "=f"(v.z), "=f"(v.w) : "l"(p));
    return v;
}
__device__ __forceinline__ int4 ldcs4i(const int4* p) {
    int4 v;
    asm volatile("ld.global.cs.v4.b32 {%0,%1,%2,%3}, [%4];"
                 : "=r"(v.x), "=r"(v.y), "=r"(v.z), "=r"(v.w) : "l"(p));
    return v;
}

__global__ __launch_bounds__(NTHREADS)
void collision_fused_kernel(const float* __restrict__ traj,
                            const float* __restrict__ gt,
                            const float4* __restrict__ corners,
                            const int4* __restrict__ mask4,
                            float* __restrict__ out)
{
    __shared__ float4 sbox[F_FRAMES];   // (xmax, ymax, xmin, ymin)
    if (threadIdx.x < F_FRAMES) {
        int f = threadIdx.x;
        float x  = traj[f * 2 + 0];
        float y  = traj[f * 2 + 1];
        float th = gt[f * 3 + 2];
        float c, s;
        __sincosf(th, &s, &c);
        const float hw = W_BOX * 0.5f, hh = H_BOX * 0.5f;
        const float lx[4] = { hw,  hw, -hw, -hw };
        const float ly[4] = {-hh,  hh,  hh, -hh };
        float xmax = -1e30f, xmin = 1e30f, ymax = -1e30f, ymin = 1e30f;
#pragma unroll
        for (int k = 0; k < 4; k++) {
            float cx =  c * lx[k] + s * ly[k] + x;   // rot = [[c,s],[-s,c]]
            float cy = -s * lx[k] + c * ly[k] + y;
            xmax = fmaxf(xmax, cx); xmin = fminf(xmin, cx);
            ymax = fmaxf(ymax, cy); ymin = fminf(ymin, cy);
        }
        sbox[f] = make_float4(xmax, ymax, xmin, ymin);
    }
    __syncthreads();

    float acc = 0.0f;
    const unsigned stride = gridDim.x * blockDim.x;
    for (unsigned q = blockIdx.x * blockDim.x + threadIdx.x;
         q < NQUADS; q += stride) {
        int4 m = ldcs4i(&mask4[q]);
        const float4* cb = corners + (size_t)q * 8u;
        unsigned f = (q * 4u) / N_PTS;          // constant within a quad
        float4 b = sbox[f];
        int mm[4] = { m.x, m.y, m.z, m.w };
#pragma unroll
        for (int i = 0; i < 4; i++) {
            float4 c0 = ldcs4(cb + i * 2 + 0);
            float4 c1 = ldcs4(cb + i * 2 + 1);
            float xb1 = fmaxf(fmaxf(c0.x, c0.z), fmaxf(c1.x, c1.z));
            float xb2 = fminf(fminf(c0.x, c0.z), fminf(c1.x, c1.z));
            float yb1 = fmaxf(fmaxf(c0.y, c0.w), fmaxf(c1.y, c1.w));
            float yb2 = fminf(fminf(c0.y, c0.w), fminf(c1.y, c1.w));
            float w = fmaxf(0.0f, fminf(b.x, xb1) - fmaxf(b.z, xb2));
            float h = fmaxf(0.0f, fminf(b.y, yb1) - fmaxf(b.w, yb2));
            acc += mm[i] ? (w * h) : 0.0f;
        }
    }

    // warp reduce
#pragma unroll
    for (int o = 16; o > 0; o >>= 1)
        acc += __shfl_down_sync(0xffffffffu, acc, o);

    __shared__ float ws[NTHREADS / 32];
    if ((threadIdx.x & 31) == 0) ws[threadIdx.x >> 5] = acc;
    __syncthreads();
    if (threadIdx.x == 0) {
        float v = 0.0f;
#pragma unroll
        for (int i = 0; i < NTHREADS / 32; i++) v += ws[i];
        atomicAdd(out, v);   // WEIGHT = 1.0
    }
}

extern "C" void kernel_launch(void* const* d_in, const int* in_sizes, int n_in,
                              void* d_out, int out_size)
{
    const float* traj = (const float*)d_in[0];
    const float* gt   = (const float*)d_in[1];
    const float4* corners = (const float4*)d_in[3];
    const int4* mask4 = (const int4*)d_in[4];
    float* out = (float*)d_out;

    cudaMemsetAsync(out, 0, sizeof(float));
    collision_fused_kernel<<<NBLOCKS, NTHREADS>>>(traj, gt, corners, mask4, out);
}

// round 4
// speedup vs baseline: 1.3982x; 1.3982x over previous
#include <cuda_runtime.h>

// CollisionLoss — single fused kernel, coalesced item-per-thread with
// unroll-by-4 strided batching (R3 post-mortem: per-thread-contiguous
// float4 blocks destroyed warp coalescing and bound L1 at 78%).
//
//  d_in[0] sdc_traj_all        (1, F, 2) f32
//  d_in[1] sdc_planning_gt     (1, F, 3) f32  (theta = [...,2])
//  d_in[2] sdc_planning_gt_mask (unused)
//  d_in[3] future_gt_corners   (F, N, 4, 2) f32  [192 MB]
//  d_in[4] box_mask            (F, N) bool as int32 [24 MB]
// output: 1 x f32

#define F_FRAMES 6
#define N_PTS    1000000u
#define TOTAL    (F_FRAMES * N_PTS)
#define W_BOX    2.35f                 /* 1.85 + 0.5 */
#define H_BOX    4.584f                /* 4.084 + 0.5 */

#define NTHREADS 256
#define NBLOCKS  2368                  /* 148 SMs * 16 */
#define UNROLL   4

__device__ __forceinline__ float4 ldcs4(const float4* p) {
    float4 v;
    asm volatile("ld.global.cs.v4.f32 {%0,%1,%2,%3}, [%4];"
                 : "=f"(v.x), "=f"(v.y), "=f"(v.z), "=f"(v.w) : "l"(p));
    return v;
}
__device__ __forceinline__ int ldcsi(const int* p) {
    int v;
    asm volatile("ld.global.cs.b32 %0, [%1];" : "=r"(v) : "l"(p));
    return v;
}

__global__ __launch_bounds__(NTHREADS)
void collision_fused_kernel(const float* __restrict__ traj,
                            const float* __restrict__ gt,
                            const float4* __restrict__ corners,
                            const int* __restrict__ mask,
                            float* __restrict__ out)
{
    __shared__ float4 sbox[F_FRAMES];   // (xmax, ymax, xmin, ymin)
    if (threadIdx.x < F_FRAMES) {
        int f = threadIdx.x;
        float x  = traj[f * 2 + 0];
        float y  = traj[f * 2 + 1];
        float th = gt[f * 3 + 2];
        float c, s;
        __sincosf(th, &s, &c);
        const float hw = W_BOX * 0.5f, hh = H_BOX * 0.5f;
        const float lx[4] = { hw,  hw, -hw, -hw };
        const float ly[4] = {-hh,  hh,  hh, -hh };
        float xmax = -1e30f, xmin = 1e30f, ymax = -1e30f, ymin = 1e30f;
#pragma unroll
        for (int k = 0; k < 4; k++) {
            float cx =  c * lx[k] + s * ly[k] + x;   // rot = [[c,s],[-s,c]]
            float cy = -s * lx[k] + c * ly[k] + y;
            xmax = fmaxf(xmax, cx); xmin = fminf(xmin, cx);
            ymax = fmaxf(ymax, cy); ymin = fminf(ymin, cy);
        }
        sbox[f] = make_float4(xmax, ymax, xmin, ymin);
    }
    __syncthreads();

    const unsigned stride = gridDim.x * blockDim.x;        // 606,208
    const unsigned tid0   = blockIdx.x * blockDim.x + threadIdx.x;

    float acc = 0.0f;
    for (unsigned base = tid0; base < TOTAL; base += stride * UNROLL) {
        unsigned items[UNROLL];
        bool     ok[UNROLL];
        float4   c0[UNROLL], c1[UNROLL];
        int      m[UNROLL];
#pragma unroll
        for (int k = 0; k < UNROLL; k++) {
            items[k] = base + (unsigned)k * stride;
            ok[k] = items[k] < TOTAL;
            unsigned it = ok[k] ? items[k] : 0u;
            c0[k] = ldcs4(&corners[(size_t)it * 2u + 0u]);
            c1[k] = ldcs4(&corners[(size_t)it * 2u + 1u]);
            m[k]  = ldcsi(&mask[it]);
        }
#pragma unroll
        for (int k = 0; k < UNROLL; k++) {
            unsigned f = items[k] / N_PTS;
            float4 b = sbox[ok[k] ? f : 0u];
            float xb1 = fmaxf(fmaxf(c0[k].x, c0[k].z), fmaxf(c1[k].x, c1[k].z));
            float xb2 = fminf(fminf(c0[k].x, c0[k].z), fminf(c1[k].x, c1[k].z));
            float yb1 = fmaxf(fmaxf(c0[k].y, c0[k].w), fmaxf(c1[k].y, c1[k].w));
            float yb2 = fminf(fminf(c0[k].y, c0[k].w), fminf(c1[k].y, c1[k].w));
            float w = fmaxf(0.0f, fminf(b.x, xb1) - fmaxf(b.z, xb2));
            float h = fmaxf(0.0f, fminf(b.y, yb1) - fmaxf(b.w, yb2));
            acc += (ok[k] && m[k]) ? (w * h) : 0.0f;
        }
    }

    // warp reduce
#pragma unroll
    for (int o = 16; o > 0; o >>= 1)
        acc += __shfl_down_sync(0xffffffffu, acc, o);

    __shared__ float ws[NTHREADS / 32];
    if ((threadIdx.x & 31) == 0) ws[threadIdx.x >> 5] = acc;
    __syncthreads();
    if (threadIdx.x == 0) {
        float v = 0.0f;
#pragma unroll
        for (int i = 0; i < NTHREADS / 32; i++) v += ws[i];
        atomicAdd(out, v);   // WEIGHT = 1.0
    }
}

extern "C" void kernel_launch(void* const* d_in, const int* in_sizes, int n_in,
                              void* d_out, int out_size)
{
    const float* traj = (const float*)d_in[0];
    const float* gt   = (const float*)d_in[1];
    const float4* corners = (const float4*)d_in[3];
    const int* mask = (const int*)d_in[4];
    float* out = (float*)d_out;

    cudaMemsetAsync(out, 0, sizeof(float));
    collision_fused_kernel<<<NBLOCKS, NTHREADS>>>(traj, gt, corners, mask, out);
}

// round 5
// speedup vs baseline: 1.3993x; 1.0008x over previous
#include <cuda_runtime.h>

// CollisionLoss — fused kernel, warp-cooperative dense loading.
// R4 post-mortem: 32B-lane-stride LDG.128s cost 8 lines/request. Here each
// warp owns an aligned 32-item chunk; corner loads are fully dense (4 lines
// per LDG.128) and item halves are merged across adjacent lanes via shfl_xor.
//
//  d_in[0] sdc_traj_all        (1, F, 2) f32
//  d_in[1] sdc_planning_gt     (1, F, 3) f32  (theta = [...,2])
//  d_in[2] sdc_planning_gt_mask (unused)
//  d_in[3] future_gt_corners   (F, N, 4, 2) f32  [192 MB]
//  d_in[4] box_mask            (F, N) bool as int32 [24 MB]
// output: 1 x f32

#define F_FRAMES 6
#define N_PTS    1000000u
#define TOTAL    (F_FRAMES * N_PTS)
#define NCHUNKS  (TOTAL / 32u)         /* 187,500 ; N_PTS % 32 == 0 */
#define W_BOX    2.35f
#define H_BOX    4.584f

#define NTHREADS 256
#define NBLOCKS  2368                  /* 148 SMs * 16 -> 18,944 warps */

__device__ __forceinline__ float4 ldcs4(const float4* p) {
    float4 v;
    asm volatile("ld.global.cs.v4.f32 {%0,%1,%2,%3}, [%4];"
                 : "=f"(v.x), "=f"(v.y), "=f"(v.z), "=f"(v.w) : "l"(p));
    return v;
}
__device__ __forceinline__ int ldcsi(const int* p) {
    int v;
    asm volatile("ld.global.cs.b32 %0, [%1];" : "=r"(v) : "l"(p));
    return v;
}

struct ChunkData { float4 v0, v1; int m; };

__device__ __forceinline__ ChunkData load_chunk(const float4* __restrict__ corners,
                                                const int* __restrict__ mask,
                                                unsigned c, unsigned lane)
{
    ChunkData d;
    const float4* p = corners + (size_t)c * 64u;   // 32 items * 2 float4
    d.v0 = ldcs4(p + lane);
    d.v1 = ldcs4(p + 32u + lane);
    d.m  = ldcsi(mask + c * 32u + lane);
    return d;
}

// half-extents of one float4 (two corners), merged with partner lane (xor 1)
__device__ __forceinline__ void pair_extents(float4 v, float& x1, float& x2,
                                             float& y1, float& y2)
{
    float hx1 = fmaxf(v.x, v.z), hx2 = fminf(v.x, v.z);
    float hy1 = fmaxf(v.y, v.w), hy2 = fminf(v.y, v.w);
    x1 = fmaxf(hx1, __shfl_xor_sync(0xffffffffu, hx1, 1));
    x2 = fminf(hx2, __shfl_xor_sync(0xffffffffu, hx2, 1));
    y1 = fmaxf(hy1, __shfl_xor_sync(0xffffffffu, hy1, 1));
    y2 = fminf(hy2, __shfl_xor_sync(0xffffffffu, hy2, 1));
}

__device__ __forceinline__ float chunk_accum(const ChunkData& d, float4 b,
                                             unsigned lane)
{
    float xb1, xb2, yb1, yb2;
    // round 0: items chunkBase + [0,16), item j held by lanes (2j, 2j+1)
    pair_extents(d.v0, xb1, xb2, yb1, yb2);
    float w0 = fmaxf(0.0f, fminf(b.x, xb1) - fmaxf(b.z, xb2));
    float h0 = fmaxf(0.0f, fminf(b.y, yb1) - fmaxf(b.w, yb2));
    float t0 = w0 * h0;
    // round 1: items chunkBase + [16,32)
    pair_extents(d.v1, xb1, xb2, yb1, yb2);
    float w1 = fmaxf(0.0f, fminf(b.x, xb1) - fmaxf(b.z, xb2));
    float h1 = fmaxf(0.0f, fminf(b.y, yb1) - fmaxf(b.w, yb2));
    float t1 = w1 * h1;

    int mr0 = __shfl_sync(0xffffffffu, d.m, lane >> 1);
    int mr1 = __shfl_sync(0xffffffffu, d.m, 16u + (lane >> 1));
    // even lane accumulates its pair's round-0 item, odd lane round-1 item
    bool even = (lane & 1u) == 0u;
    float te = even ? (mr0 ? t0 : 0.0f) : (mr1 ? t1 : 0.0f);
    return te;
}

__global__ __launch_bounds__(NTHREADS)
void collision_fused_kernel(const float* __restrict__ traj,
                            const float* __restrict__ gt,
                            const float4* __restrict__ corners,
                            const int* __restrict__ mask,
                            float* __restrict__ out)
{
    __shared__ float4 sbox[F_FRAMES];   // (xmax, ymax, xmin, ymin)
    if (threadIdx.x < F_FRAMES) {
        int f = threadIdx.x;
        float x  = traj[f * 2 + 0];
        float y  = traj[f * 2 + 1];
        float th = gt[f * 3 + 2];
        float c, s;
        __sincosf(th, &s, &c);
        const float hw = W_BOX * 0.5f, hh = H_BOX * 0.5f;
        const float lx[4] = { hw,  hw, -hw, -hw };
        const float ly[4] = {-hh,  hh,  hh, -hh };
        float xmax = -1e30f, xmin = 1e30f, ymax = -1e30f, ymin = 1e30f;
#pragma unroll
        for (int k = 0; k < 4; k++) {
            float cx =  c * lx[k] + s * ly[k] + x;   // rot = [[c,s],[-s,c]]
            float cy = -s * lx[k] + c * ly[k] + y;
            xmax = fmaxf(xmax, cx); xmin = fminf(xmin, cx);
            ymax = fmaxf(ymax, cy); ymin = fminf(ymin, cy);
        }
        sbox[f] = make_float4(xmax, ymax, xmin, ymin);
    }
    __syncthreads();

    const unsigned lane = threadIdx.x & 31u;
    const unsigned gw   = (blockIdx.x * blockDim.x + threadIdx.x) >> 5;
    const unsigned nw   = (gridDim.x * blockDim.x) >> 5;   // 18,944 warps

    float acc = 0.0f;
    unsigned c = gw;
    // unroll-2 over chunks for deeper MLP (6 outstanding LDGs)
    for (; c + nw < NCHUNKS; c += 2u * nw) {
        ChunkData dA = load_chunk(corners, mask, c, lane);
        ChunkData dB = load_chunk(corners, mask, c + nw, lane);
        float4 bA = sbox[(c * 32u) / N_PTS];
        float4 bB = sbox[((c + nw) * 32u) / N_PTS];
        acc += chunk_accum(dA, bA, lane);
        acc += chunk_accum(dB, bB, lane);
    }
    if (c < NCHUNKS) {
        ChunkData d = load_chunk(corners, mask, c, lane);
        float4 b = sbox[(c * 32u) / N_PTS];
        acc += chunk_accum(d, b, lane);
    }

    // warp reduce
#pragma unroll
    for (int o = 16; o > 0; o >>= 1)
        acc += __shfl_down_sync(0xffffffffu, acc, o);

    __shared__ float ws[NTHREADS / 32];
    if ((threadIdx.x & 31) == 0) ws[threadIdx.x >> 5] = acc;
    __syncthreads();
    if (threadIdx.x == 0) {
        float v = 0.0f;
#pragma unroll
        for (int i = 0; i < NTHREADS / 32; i++) v += ws[i];
        atomicAdd(out, v);   // WEIGHT = 1.0
    }
}

extern "C" void kernel_launch(void* const* d_in, const int* in_sizes, int n_in,
                              void* d_out, int out_size)
{
    const float* traj = (const float*)d_in[0];
    const float* gt   = (const float*)d_in[1];
    const float4* corners = (const float4*)d_in[3];
    const int* mask = (const int*)d_in[4];
    float* out = (float*)d_out;

    cudaMemsetAsync(out, 0, sizeof(float));
    collision_fused_kernel<<<NBLOCKS, NTHREADS>>>(traj, gt, corners, mask, out);
}